// round 2
// baseline (speedup 1.0000x reference)
#include <cuda_runtime.h>

#define NN 10000
#define NE 100000
#define NET (NE + NN)
#define FD 768
#define HH 6
#define CH 128
#define BGR 64
#define OC 128

// ---------------- scratch (device globals: allocation-free) ----------------
__device__ float g_hx[(size_t)NN * FD];
__device__ float g_y[(size_t)NN * FD];
__device__ float g_as[NN * HH];
__device__ float g_ad[NN * HH];
__device__ int   g_deg[NN];
__device__ int   g_ptr[NN + 1];
__device__ int   g_cur[NN];
__device__ int   g_csr[NET];
__device__ float g_colsum[FD];
__device__ float g_colsum2[FD];
__device__ float g_scale[FD];
__device__ float g_shift[FD];
__device__ float g_lin[(size_t)NN * OC];

// monotone float<->uint encoding for atomicMax on floats
__device__ __forceinline__ unsigned fenc(float f) {
    unsigned u = __float_as_uint(f);
    return (u & 0x80000000u) ? ~u : (u | 0x80000000u);
}
__device__ __forceinline__ float fdec(unsigned u) {
    return (u & 0x80000000u) ? __uint_as_float(u ^ 0x80000000u)
                             : __uint_as_float(~u);
}
#define ENC_NEG_INF 0x007FFFFFu  // fenc(-inf)

// ---------------- CSR build ----------------
__global__ void k_zero_deg() {
    int i = blockIdx.x * blockDim.x + threadIdx.x;
    if (i < NN) g_deg[i] = 0;
}

__global__ void k_count(const int* __restrict__ adj) {
    int i = blockIdx.x * blockDim.x + threadIdx.x;
    if (i >= NET) return;
    int d = (i < NE) ? adj[NE + i] : (i - NE);
    atomicAdd(&g_deg[d], 1);
}

__global__ void k_scan() {
    __shared__ int sh[1024];
    __shared__ int soff;
    int t = threadIdx.x;
    if (t == 0) soff = 0;
    __syncthreads();
    for (int base = 0; base < NN; base += 1024) {
        int v = (base + t < NN) ? g_deg[base + t] : 0;
        sh[t] = v;
        __syncthreads();
        for (int d = 1; d < 1024; d <<= 1) {
            int y = (t >= d) ? sh[t - d] : 0;
            __syncthreads();
            sh[t] += y;
            __syncthreads();
        }
        int off = soff;
        if (base + t < NN) {
            int ex = off + sh[t] - v;
            g_ptr[base + t] = ex;
            g_cur[base + t] = ex;
        }
        __syncthreads();
        if (t == 1023) soff = off + sh[1023];
        __syncthreads();
    }
    if (t == 0) g_ptr[NN] = soff;
}

__global__ void k_scatter(const int* __restrict__ adj) {
    int i = blockIdx.x * blockDim.x + threadIdx.x;
    if (i >= NET) return;
    int s, d;
    if (i < NE) { s = adj[i]; d = adj[NE + i]; }
    else        { s = i - NE; d = i - NE; }
    int pos = atomicAdd(&g_cur[d], 1);
    g_csr[pos] = s;
}

// ---------------- GEMM: C[M,Nc] = A[M,K] @ B[K,Nc] (+bias) ----------------
// 128x128x8 tile, 256 threads, 8x8 per thread
__global__ __launch_bounds__(256) void k_gemm(
    const float* __restrict__ A, const float* __restrict__ B,
    const float* __restrict__ bias, float* __restrict__ C,
    int M, int Nc, int K)
{
    __shared__ float As[8][128];
    __shared__ float Bs[8][128];
    int t = threadIdx.x;
    int bm = blockIdx.y, bn = blockIdx.x;
    int tx = t & 15, ty = t >> 4;

    int a_row = t >> 1;
    int a_col = (t & 1) * 4;
    int b_row = t >> 5;
    int b_col = (t & 31) * 4;
    int grow = bm * 128 + a_row;
    bool arow_ok = grow < M;

    float acc[8][8];
#pragma unroll
    for (int i = 0; i < 8; i++)
#pragma unroll
        for (int j = 0; j < 8; j++) acc[i][j] = 0.f;

    for (int k0 = 0; k0 < K; k0 += 8) {
        float4 av = make_float4(0.f, 0.f, 0.f, 0.f);
        if (arow_ok)
            av = *(const float4*)(A + (size_t)grow * K + k0 + a_col);
        As[a_col + 0][a_row] = av.x;
        As[a_col + 1][a_row] = av.y;
        As[a_col + 2][a_row] = av.z;
        As[a_col + 3][a_row] = av.w;
        *(float4*)&Bs[b_row][b_col] =
            *(const float4*)(B + (size_t)(k0 + b_row) * Nc + bn * 128 + b_col);
        __syncthreads();
#pragma unroll
        for (int k = 0; k < 8; k++) {
            float a[8], b[8];
            *(float4*)&a[0] = *(float4*)&As[k][ty * 4];
            *(float4*)&a[4] = *(float4*)&As[k][ty * 4 + 64];
            *(float4*)&b[0] = *(float4*)&Bs[k][tx * 4];
            *(float4*)&b[4] = *(float4*)&Bs[k][tx * 4 + 64];
#pragma unroll
            for (int i = 0; i < 8; i++)
#pragma unroll
                for (int j = 0; j < 8; j++)
                    acc[i][j] = fmaf(a[i], b[j], acc[i][j]);
        }
        __syncthreads();
    }

#pragma unroll
    for (int i = 0; i < 8; i++) {
        int ri = ty * 4 + (i & 3) + ((i >= 4) ? 64 : 0);
        int r = bm * 128 + ri;
        if (r >= M) continue;
#pragma unroll
        for (int j = 0; j < 8; j++) {
            int cj = tx * 4 + (j & 3) + ((j >= 4) ? 64 : 0);
            int c = bn * 128 + cj;
            float v = acc[i][j];
            if (bias) v += bias[c];
            C[(size_t)r * Nc + c] = v;
        }
    }
}

// ---------------- attention scores: as/ad[n,h] = <hx[n,h,:], att[h,:]> ----------------
__global__ __launch_bounds__(256) void k_att(
    const float* __restrict__ hx, const float* __restrict__ atts,
    const float* __restrict__ attd)
{
    int gt = blockIdx.x * blockDim.x + threadIdx.x;
    int w = gt >> 5, lane = gt & 31;
    if (w >= NN * HH) return;
    int n = w / HH, h = w - n * HH;
    const float* row = hx + (size_t)n * FD + h * CH;
    const float* vs = atts + h * CH;
    const float* vd = attd + h * CH;
    float sa = 0.f, sd = 0.f;
#pragma unroll
    for (int c = lane; c < CH; c += 32) {
        float v = row[c];
        sa += v * vs[c];
        sd += v * vd[c];
    }
#pragma unroll
    for (int o = 16; o; o >>= 1) {
        sa += __shfl_down_sync(0xffffffffu, sa, o);
        sd += __shfl_down_sync(0xffffffffu, sd, o);
    }
    if (lane == 0) { g_as[w] = sa; g_ad[w] = sd; }
}

// ---------------- fused softmax + aggregate + bias + relu, per dst node ----------------
__global__ __launch_bounds__(256) void k_agg(
    const float* __restrict__ hx, const float* __restrict__ bias,
    float* __restrict__ out)
{
    int d = blockIdx.x;
    int t = threadIdx.x;
    __shared__ float    s_ad[HH];
    __shared__ unsigned s_m[HH];
    __shared__ float    s_mf[HH];
    __shared__ float    s_s[HH];
    __shared__ float    s_w[128 * HH];
    __shared__ int      s_src[128];

    int p0 = g_ptr[d], p1 = g_ptr[d + 1];
    int deg = p1 - p0;
    if (t < HH) {
        s_ad[t] = g_ad[d * HH + t];
        s_m[t] = ENC_NEG_INF;
        s_s[t] = 0.f;
    }
    __syncthreads();

    // stage 1: per-head max of leaky_relu(as[src]+ad[dst])
    float lm[HH];
#pragma unroll
    for (int h = 0; h < HH; h++) lm[h] = -3.0e38f;
    for (int i = t; i < deg; i += 256) {
        int s = g_csr[p0 + i];
#pragma unroll
        for (int h = 0; h < HH; h++) {
            float e = g_as[s * HH + h] + s_ad[h];
            e = (e > 0.f) ? e : 0.2f * e;
            lm[h] = fmaxf(lm[h], e);
        }
    }
#pragma unroll
    for (int h = 0; h < HH; h++) atomicMax(&s_m[h], fenc(lm[h]));
    __syncthreads();
    if (t < HH) s_mf[t] = fdec(s_m[t]);
    __syncthreads();

    // stage 2: accumulate exp(e-m)*hx[src] and sums, chunked
    float a0 = 0.f, a1 = 0.f, a2 = 0.f;
    int c0 = t, c1 = t + 256, c2 = t + 512;
    int h0 = c0 >> 7, h1 = c1 >> 7, h2 = c2 >> 7;
    for (int cb = 0; cb < deg; cb += 128) {
        int cl = min(128, deg - cb);
        for (int j = t; j < cl * HH; j += 256) {
            int i = j / HH, h = j - i * HH;
            int s = g_csr[p0 + cb + i];
            if (h == 0) s_src[i] = s;
            float e = g_as[s * HH + h] + s_ad[h];
            e = (e > 0.f) ? e : 0.2f * e;
            float w = __expf(e - s_mf[h]);
            s_w[i * HH + h] = w;
            atomicAdd(&s_s[h], w);
        }
        __syncthreads();
        for (int i = 0; i < cl; i++) {
            const float* row = hx + (size_t)s_src[i] * FD;
            a0 += s_w[i * HH + h0] * row[c0];
            a1 += s_w[i * HH + h1] * row[c1];
            a2 += s_w[i * HH + h2] * row[c2];
        }
        __syncthreads();
    }

    float r0 = a0 / s_s[h0] + bias[c0];
    float r1 = a1 / s_s[h1] + bias[c1];
    float r2 = a2 / s_s[h2] + bias[c2];
    size_t base = (size_t)d * FD;
    out[base + c0] = fmaxf(r0, 0.f);
    out[base + c1] = fmaxf(r1, 0.f);
    out[base + c2] = fmaxf(r2, 0.f);
}

// ---------------- batch norm ----------------
__global__ void k_zero_cols() {
    int i = blockIdx.x * blockDim.x + threadIdx.x;
    if (i < FD) { g_colsum[i] = 0.f; g_colsum2[i] = 0.f; }
}

__global__ __launch_bounds__(256) void k_bn_stats(const float* __restrict__ y) {
    int b = blockIdx.x;
    int rows_per = (NN + gridDim.x - 1) / gridDim.x;
    int r0 = b * rows_per;
    int r1 = min(NN, r0 + rows_per);
    int t = threadIdx.x;
    float s[3] = {0.f, 0.f, 0.f}, q[3] = {0.f, 0.f, 0.f};
    for (int r = r0; r < r1; r++) {
        const float* row = y + (size_t)r * FD;
#pragma unroll
        for (int k = 0; k < 3; k++) {
            float v = row[t + k * 256];
            s[k] += v;
            q[k] += v * v;
        }
    }
#pragma unroll
    for (int k = 0; k < 3; k++) {
        atomicAdd(&g_colsum[t + k * 256], s[k]);
        atomicAdd(&g_colsum2[t + k * 256], q[k]);
    }
}

__global__ void k_bn_fin(const float* __restrict__ g, const float* __restrict__ be) {
    int c = blockIdx.x * blockDim.x + threadIdx.x;
    if (c >= FD) return;
    float mu = g_colsum[c] * (1.0f / NN);
    float var = g_colsum2[c] * (1.0f / NN) - mu * mu;
    float sc = g[c] * rsqrtf(var + 1e-5f);
    g_scale[c] = sc;
    g_shift[c] = be[c] - mu * sc;
}

__global__ void k_bn_apply(float* __restrict__ y) {
    int i = blockIdx.x * blockDim.x + threadIdx.x;
    if (i >= NN * FD) return;
    int c = i % FD;
    y[i] = y[i] * g_scale[c] + g_shift[c];
}

// ---------------- global max pool over graphs ----------------
__global__ void k_pool_init(unsigned* __restrict__ out) {
    int i = blockIdx.x * blockDim.x + threadIdx.x;
    if (i < BGR * OC) out[i] = ENC_NEG_INF;
}

__global__ void k_pool(const int* __restrict__ ibatch, unsigned* __restrict__ out) {
    int i = blockIdx.x * blockDim.x + threadIdx.x;
    if (i >= NN * OC) return;
    int n = i / OC, c = i - n * OC;
    int g = ibatch[n];
    atomicMax(&out[g * OC + c], fenc(g_lin[i]));
}

__global__ void k_pool_dec(float* __restrict__ out) {
    int i = blockIdx.x * blockDim.x + threadIdx.x;
    if (i < BGR * OC) {
        unsigned u = ((unsigned*)out)[i];
        out[i] = fdec(u);
    }
}

// ---------------- launch ----------------
extern "C" void kernel_launch(void* const* d_in, const int* in_sizes, int n_in,
                              void* d_out, int out_size) {
    const float* x   = (const float*)d_in[0];
    const int*   adj = (const int*)d_in[1];
    const int*   ib  = (const int*)d_in[2];
    const float* W1  = (const float*)d_in[3];
    const float* as1 = (const float*)d_in[4];
    const float* ad1 = (const float*)d_in[5];
    const float* b1  = (const float*)d_in[6];
    const float* g1  = (const float*)d_in[7];
    const float* be1 = (const float*)d_in[8];
    const float* W2  = (const float*)d_in[9];
    const float* as2 = (const float*)d_in[10];
    const float* ad2 = (const float*)d_in[11];
    const float* b2  = (const float*)d_in[12];
    const float* g2  = (const float*)d_in[13];
    const float* be2 = (const float*)d_in[14];
    const float* lW  = (const float*)d_in[15];
    const float* lb  = (const float*)d_in[16];

    float *hx, *y, *lin;
    cudaGetSymbolAddress((void**)&hx, g_hx);
    cudaGetSymbolAddress((void**)&y, g_y);
    cudaGetSymbolAddress((void**)&lin, g_lin);

    // CSR build
    k_zero_deg<<<(NN + 255) / 256, 256>>>();
    k_count<<<(NET + 255) / 256, 256>>>(adj);
    k_scan<<<1, 1024>>>();
    k_scatter<<<(NET + 255) / 256, 256>>>(adj);

    dim3 gemm_grid(FD / 128, (NN + 127) / 128);

    // layer 1
    k_gemm<<<gemm_grid, 256>>>(x, W1, nullptr, hx, NN, FD, 256);
    k_att<<<(NN * HH * 32 + 255) / 256, 256>>>(hx, as1, ad1);
    k_agg<<<NN, 256>>>(hx, b1, y);
    k_zero_cols<<<3, 256>>>();
    k_bn_stats<<<80, 256>>>(y);
    k_bn_fin<<<3, 256>>>(g1, be1);
    k_bn_apply<<<(NN * FD + 255) / 256, 256>>>(y);

    // layer 2
    k_gemm<<<gemm_grid, 256>>>(y, W2, nullptr, hx, NN, FD, FD);
    k_att<<<(NN * HH * 32 + 255) / 256, 256>>>(hx, as2, ad2);
    k_agg<<<NN, 256>>>(hx, b2, y);
    k_zero_cols<<<3, 256>>>();
    k_bn_stats<<<80, 256>>>(y);
    k_bn_fin<<<3, 256>>>(g2, be2);
    k_bn_apply<<<(NN * FD + 255) / 256, 256>>>(y);

    // linear head
    dim3 lin_grid(OC / 128, (NN + 127) / 128);
    k_gemm<<<lin_grid, 256>>>(y, lW, lb, lin, NN, OC, FD);

    // pooling
    k_pool_init<<<(BGR * OC + 255) / 256, 256>>>((unsigned*)d_out);
    k_pool<<<(NN * OC + 255) / 256, 256>>>(ib, (unsigned*)d_out);
    k_pool_dec<<<(BGR * OC + 255) / 256, 256>>>((float*)d_out);
}